// round 2
// baseline (speedup 1.0000x reference)
#include <cuda_runtime.h>

#define PI_F 3.14159265358979323846f

// ---------------------------------------------------------------------------
// 1-qubit complex 2x2 gate apply on 16-amplitude state held in registers.
// ---------------------------------------------------------------------------
template <int ST>
__device__ __forceinline__ void apply1q(float* sr, float* si,
                                        const float4 g0, const float4 g1) {
#pragma unroll
    for (int m = 0; m < 8; ++m) {
        const int i0 = ((m & ~(ST - 1)) << 1) | (m & (ST - 1));
        const int i1 = i0 + ST;
        const float ar = sr[i0], ai = si[i0];
        const float br = sr[i1], bi = si[i1];
        sr[i0] = g0.x * ar - g0.y * ai + g0.z * br - g0.w * bi;
        si[i0] = g0.x * ai + g0.y * ar + g0.z * bi + g0.w * br;
        sr[i1] = g1.x * ar - g1.y * ai + g1.z * br - g1.w * bi;
        si[i1] = g1.x * ai + g1.y * ar + g1.z * bi + g1.w * br;
    }
}

template <int CM, int TM>
__device__ __forceinline__ void cnot(float* sr, float* si) {
#pragma unroll
    for (int i = 0; i < 16; ++i) {
        if ((i & CM) && !(i & TM)) {
            const int j = i | TM;
            float t;
            t = sr[i]; sr[i] = sr[j]; sr[j] = t;
            t = si[i]; si[i] = si[j]; si[j] = t;
        }
    }
}

template <int R>
__device__ __forceinline__ void do_layer(float* sr, float* si,
                                         const float4 (*g)[2]) {
    apply1q<8>(sr, si, g[0][0], g[0][1]);
    apply1q<4>(sr, si, g[1][0], g[1][1]);
    apply1q<2>(sr, si, g[2][0], g[2][1]);
    apply1q<1>(sr, si, g[3][0], g[3][1]);
    cnot<(8 >> 0), (8 >> ((0 + R) % 4))>(sr, si);
    cnot<(8 >> 1), (8 >> ((1 + R) % 4))>(sr, si);
    cnot<(8 >> 2), (8 >> ((2 + R) % 4))>(sr, si);
    cnot<(8 >> 3), (8 >> ((3 + R) % 4))>(sr, si);
}

// ---------------------------------------------------------------------------
// 6-shuffle reduction of 4 accumulators over 32 lanes.
// Result: lanes [8q, 8q+8) all hold the full sum of accumulator q.
// ---------------------------------------------------------------------------
__device__ __forceinline__ float reduce4x32(float a0, float a1, float a2,
                                            float a3, int lane) {
    float s1 = (lane & 16) ? a0 : a2;
    float r1 = __shfl_xor_sync(0xffffffffu, s1, 16);
    float t  = ((lane & 16) ? a2 : a0) + r1;
    float s2 = (lane & 16) ? a1 : a3;
    float r2 = __shfl_xor_sync(0xffffffffu, s2, 16);
    float u  = ((lane & 16) ? a3 : a1) + r2;
    float s3 = (lane & 8) ? t : u;
    float r3 = __shfl_xor_sync(0xffffffffu, s3, 8);
    float c  = ((lane & 8) ? u : t) + r3;
    c += __shfl_xor_sync(0xffffffffu, c, 4);
    c += __shfl_xor_sync(0xffffffffu, c, 2);
    c += __shfl_xor_sync(0xffffffffu, c, 1);
    return c;
}

__device__ __forceinline__ float dot4(const float4 a, const float4 b) {
    return fmaf(a.x, b.x, fmaf(a.y, b.y, fmaf(a.z, b.z, a.w * b.w)));
}

// Block: 256 threads = 8 warps. 64 rows per block.
// Phase 1: warp (K = warp&3, G = warp>>2) computes the 128-column K-slice of
//          rows G*32 .. G*32+31, reduces, writes partials to smem.
// Phase 2: threads 0..63 run the quantum circuit, one row per thread.
__global__ __launch_bounds__(256, 3) void vqc_kernel(
    const float* __restrict__ x,        // [B, 512]
    const float* __restrict__ W_pre,    // [4, 512]
    const float* __restrict__ b_pre,    // [4]
    const float* __restrict__ q_weights,// [6, 4, 3]
    const float* __restrict__ W_post,   // [10, 4]
    const float* __restrict__ b_post,   // [10]
    float* __restrict__ out,            // [B, 10]
    int B)
{
    __shared__ float4 g_sh[24][2];      // 24 Rot gates, 8 floats each
    __shared__ float  part[16][64];     // [warpK*4 + qubit][local row]
    __shared__ float  wpost_sh[40];
    __shared__ float  bpost_sh[10];

    const int tid   = threadIdx.x;
    const int lane  = tid & 31;
    const int warp  = tid >> 5;
    const int warpK = warp & 3;         // K-slice: columns warpK*128 ..
    const int rowG  = warp >> 2;        // row group: rows rowG*32 ..
    const int blockBase = blockIdx.x * 64;

    // ---- Precompute batch-independent Rot gates into smem ----
    if (tid < 24) {
        const float phi = q_weights[tid * 3 + 0];
        const float th  = q_weights[tid * 3 + 1];
        const float om  = q_weights[tid * 3 + 2];
        float c, s, cp, sp, cm, sm;
        sincosf(0.5f * th, &s, &c);
        sincosf(0.5f * (phi + om), &sp, &cp);
        sincosf(0.5f * (phi - om), &sm, &cm);
        g_sh[tid][0] = make_float4(cp * c, -sp * c, -cm * s, -sm * s);
        g_sh[tid][1] = make_float4(cm * s, -sm * s,  cp * c,  sp * c);
    }
    if (tid >= 128 && tid < 178) {
        const int i = tid - 128;
        if (i < 40) wpost_sh[i] = W_post[i];
        else        bpost_sh[i - 40] = b_post[i - 40];
    }

    // ---- Phase 1: split-K warp-cooperative GEMV ----
    const int colBase = warpK * 128 + lane * 4;
    float4 wv[4];
#pragma unroll
    for (int w = 0; w < 4; ++w)
        wv[w] = *reinterpret_cast<const float4*>(W_pre + w * 512 + colBase);

    const int myRowBase = blockBase + rowG * 32;
    const int localBase = rowG * 32;

#pragma unroll 1
    for (int r = 0; r < 32; r += 2) {
        int row0 = myRowBase + r;
        int row1 = row0 + 1;
        if (row0 >= B) row0 = B - 1;
        if (row1 >= B) row1 = B - 1;
        const float4 xv0 = *reinterpret_cast<const float4*>(
            x + (long)row0 * 512 + colBase);
        const float4 xv1 = *reinterpret_cast<const float4*>(
            x + (long)row1 * 512 + colBase);

        const float a0 = dot4(xv0, wv[0]);
        const float a1 = dot4(xv0, wv[1]);
        const float a2 = dot4(xv0, wv[2]);
        const float a3 = dot4(xv0, wv[3]);
        const float b0 = dot4(xv1, wv[0]);
        const float b1 = dot4(xv1, wv[1]);
        const float b2 = dot4(xv1, wv[2]);
        const float b3 = dot4(xv1, wv[3]);

        const float ca = reduce4x32(a0, a1, a2, a3, lane);
        const float cb = reduce4x32(b0, b1, b2, b3, lane);

        if ((lane & 7) == 0) {
            const int q = lane >> 3;
            part[warpK * 4 + q][localBase + r]     = ca;
            part[warpK * 4 + q][localBase + r + 1] = cb;
        }
    }

    __syncthreads();
    if (warp >= 2) return;   // only warps 0,1 run the circuit

    // ---- Phase 2: thread-per-row quantum circuit ----
    const int row = blockBase + tid;    // tid in [0,64)
    const int lr  = tid;

    float p0 = part[0][lr] + part[4][lr] + part[8][lr]  + part[12][lr];
    float p1 = part[1][lr] + part[5][lr] + part[9][lr]  + part[13][lr];
    float p2 = part[2][lr] + part[6][lr] + part[10][lr] + part[14][lr];
    float p3 = part[3][lr] + part[7][lr] + part[11][lr] + part[15][lr];

    float cw[4], sw[4];
    {
        const float bp0 = __ldg(b_pre + 0), bp1 = __ldg(b_pre + 1);
        const float bp2 = __ldg(b_pre + 2), bp3 = __ldg(b_pre + 3);
        float ang;
        ang = tanhf(p0 + bp0) * PI_F; sincosf(0.5f * ang, &sw[0], &cw[0]);
        ang = tanhf(p1 + bp1) * PI_F; sincosf(0.5f * ang, &sw[1], &cw[1]);
        ang = tanhf(p2 + bp2) * PI_F; sincosf(0.5f * ang, &sw[2], &cw[2]);
        ang = tanhf(p3 + bp3) * PI_F; sincosf(0.5f * ang, &sw[3], &cw[3]);
    }

    float sr[16], si[16];
#pragma unroll
    for (int i = 0; i < 16; ++i) {
        sr[i] = ((i & 8) ? sw[0] : cw[0]) * ((i & 4) ? sw[1] : cw[1]) *
                ((i & 2) ? sw[2] : cw[2]) * ((i & 1) ? sw[3] : cw[3]);
        si[i] = 0.f;
    }

#pragma unroll 1
    for (int h = 0; h < 2; ++h) {
        const float4 (*gb)[2] = &g_sh[h * 12];
        do_layer<1>(sr, si, gb + 0);
        do_layer<2>(sr, si, gb + 4);
        do_layer<3>(sr, si, gb + 8);
    }

    float e0 = 0.f, e1 = 0.f, e2 = 0.f, e3 = 0.f;
#pragma unroll
    for (int i = 0; i < 16; ++i) {
        const float pr = sr[i] * sr[i] + si[i] * si[i];
        e0 += (i & 8) ? -pr : pr;
        e1 += (i & 4) ? -pr : pr;
        e2 += (i & 2) ? -pr : pr;
        e3 += (i & 1) ? -pr : pr;
    }

    if (row >= B) return;

    float o[10];
#pragma unroll
    for (int c = 0; c < 10; ++c) {
        o[c] = bpost_sh[c]
             + e0 * wpost_sh[c * 4 + 0] + e1 * wpost_sh[c * 4 + 1]
             + e2 * wpost_sh[c * 4 + 2] + e3 * wpost_sh[c * 4 + 3];
    }
    float2* op = reinterpret_cast<float2*>(out + (long)row * 10);
#pragma unroll
    for (int c = 0; c < 5; ++c) op[c] = make_float2(o[2 * c], o[2 * c + 1]);
}

extern "C" void kernel_launch(void* const* d_in, const int* in_sizes, int n_in,
                              void* d_out, int out_size) {
    const float* x    = (const float*)d_in[0];
    const float* Wpre = (const float*)d_in[1];
    const float* bpre = (const float*)d_in[2];
    const float* qw   = (const float*)d_in[3];
    const float* Wpo  = (const float*)d_in[4];
    const float* bpo  = (const float*)d_in[5];
    float* out = (float*)d_out;

    const int B = in_sizes[0] / 512;
    const int grid = (B + 63) / 64;
    vqc_kernel<<<grid, 256>>>(x, Wpre, bpre, qw, Wpo, bpo, out, B);
}

// round 3
// speedup vs baseline: 1.2965x; 1.2965x over previous
#include <cuda_runtime.h>

#define PI_F 3.14159265358979323846f

// ---------------------------------------------------------------------------
// 1-qubit complex 2x2 gate apply on 16-amplitude register state.
// ---------------------------------------------------------------------------
template <int ST>
__device__ __forceinline__ void apply1q(float* sr, float* si,
                                        const float4 g0, const float4 g1) {
#pragma unroll
    for (int m = 0; m < 8; ++m) {
        const int i0 = ((m & ~(ST - 1)) << 1) | (m & (ST - 1));
        const int i1 = i0 + ST;
        const float ar = sr[i0], ai = si[i0];
        const float br = sr[i1], bi = si[i1];
        sr[i0] = g0.x * ar - g0.y * ai + g0.z * br - g0.w * bi;
        si[i0] = g0.x * ai + g0.y * ar + g0.z * bi + g0.w * br;
        sr[i1] = g1.x * ar - g1.y * ai + g1.z * br - g1.w * bi;
        si[i1] = g1.x * ai + g1.y * ar + g1.z * bi + g1.w * br;
    }
}

template <int CM, int TM>
__device__ __forceinline__ void cnot(float* sr, float* si) {
#pragma unroll
    for (int i = 0; i < 16; ++i) {
        if ((i & CM) && !(i & TM)) {
            const int j = i | TM;
            float t;
            t = sr[i]; sr[i] = sr[j]; sr[j] = t;
            t = si[i]; si[i] = si[j]; si[j] = t;
        }
    }
}

template <int R>
__device__ __forceinline__ void do_layer(float* sr, float* si,
                                         const float4 (*g)[2]) {
    apply1q<8>(sr, si, g[0][0], g[0][1]);
    apply1q<4>(sr, si, g[1][0], g[1][1]);
    apply1q<2>(sr, si, g[2][0], g[2][1]);
    apply1q<1>(sr, si, g[3][0], g[3][1]);
    cnot<(8 >> 0), (8 >> ((0 + R) % 4))>(sr, si);
    cnot<(8 >> 1), (8 >> ((1 + R) % 4))>(sr, si);
    cnot<(8 >> 2), (8 >> ((2 + R) % 4))>(sr, si);
    cnot<(8 >> 3), (8 >> ((3 + R) % 4))>(sr, si);
}

__device__ __forceinline__ float dot4acc(const float4 a, const float4 b,
                                         float acc) {
    return fmaf(a.x, b.x, fmaf(a.y, b.y, fmaf(a.z, b.z,
           fmaf(a.w, b.w, acc))));
}

// ---------------------------------------------------------------------------
// Fused kernel. Block = 128 threads (4 warps); each block owns 128 rows.
// Grid = B/128 = 512 -> single resident wave (4 blocks/SM cap).
// Per 32-row sub-tile s: 4 quarter-K stages (128 cols each) staged through
// smem; thread (warp w, lane l) accumulates 4 qubit partials for row l over
// its 32-col slice; partials combined via one smem pass -> cos/sin of angles.
// Then every thread runs the 4-qubit circuit for its own row.
// ---------------------------------------------------------------------------
__global__ __launch_bounds__(128, 4) void vqc_fused(
    const float4* __restrict__ x4,      // [B, 128] float4
    const float4* __restrict__ Wpre4,   // [4, 128] float4
    const float* __restrict__ b_pre,    // [4]
    const float* __restrict__ q_weights,// [6, 4, 3]
    const float* __restrict__ W_post,   // [10, 4]
    const float* __restrict__ b_post,   // [10]
    float* __restrict__ out,            // [B, 10]
    int B)
{
    __shared__ float4 xt[32 * 33];      // 32 rows x 32 f4 (+1 pad)  16.9KB
    __shared__ float4 Ws[4 * 128];      // W_pre                      8KB
    __shared__ float4 part[4 * 128];    // [warp][row] 4 qubit sums   8KB
    __shared__ float2 cs[128 * 4];      // (cos,sin) per row,qubit    4KB
    __shared__ float4 g_sh[24][2];      // Rot gates                  768B
    __shared__ float  wpost_sh[40];
    __shared__ float  bpost_sh[10];

    const int tid  = threadIdx.x;
    const int lane = tid & 31;
    const int w    = tid >> 5;

    // ---- one-time smem init (covered by first barrier below) ----
    if (tid < 24) {
        const float phi = q_weights[tid * 3 + 0];
        const float th  = q_weights[tid * 3 + 1];
        const float om  = q_weights[tid * 3 + 2];
        float c, s, cp, sp, cm, sm;
        sincosf(0.5f * th, &s, &c);
        sincosf(0.5f * (phi + om), &sp, &cp);
        sincosf(0.5f * (phi - om), &sm, &cm);
        g_sh[tid][0] = make_float4(cp * c, -sp * c, -cm * s, -sm * s);
        g_sh[tid][1] = make_float4(cm * s, -sm * s,  cp * c,  sp * c);
    }
#pragma unroll
    for (int k = 0; k < 4; ++k)
        Ws[k * 128 + tid] = Wpre4[k * 128 + tid];
    if (tid >= 64 && tid < 104)      wpost_sh[tid - 64] = W_post[tid - 64];
    else if (tid >= 104 && tid < 114) bpost_sh[tid - 104] = b_post[tid - 104];

    const long rowBlk = (long)blockIdx.x * 128;

    // ---- GEMV over 4 sub-tiles of 32 rows ----
#pragma unroll 1
    for (int s = 0; s < 4; ++s) {
        const long sBase = rowBlk + s * 32;
        float a0 = 0.f, a1 = 0.f, a2 = 0.f, a3 = 0.f;

#pragma unroll 1
        for (int h = 0; h < 4; ++h) {
            // stage 32 rows x 128 cols (32 f4) -- 8 coalesced LDG.128/thread
#pragma unroll
            for (int k = 0; k < 8; ++k) {
                const int fi = k * 128 + tid;
                const int r  = fi >> 5;
                const int c  = fi & 31;
                long row = sBase + r;
                if (row >= B) row = B - 1;
                xt[r * 33 + c] = x4[row * 128 + h * 32 + c];
            }
            __syncthreads();
            // this warp's 8-f4 column slice for row `lane`
#pragma unroll
            for (int j = 0; j < 8; ++j) {
                const int c4 = w * 8 + j;
                const float4 xv = xt[lane * 33 + c4];
                const int wc = h * 32 + c4;
                a0 = dot4acc(xv, Ws[0 * 128 + wc], a0);
                a1 = dot4acc(xv, Ws[1 * 128 + wc], a1);
                a2 = dot4acc(xv, Ws[2 * 128 + wc], a2);
                a3 = dot4acc(xv, Ws[3 * 128 + wc], a3);
            }
            __syncthreads();
        }

        part[w * 128 + lane] = make_float4(a0, a1, a2, a3);
        __syncthreads();

        // combine 4 warp-partials; compute tanh -> half-angle cos/sin
        {
            const int r32 = tid >> 2;
            const int q   = tid & 3;
            const float* pf = (const float*)part;
            const float sum = pf[(0 * 128 + r32) * 4 + q]
                            + pf[(1 * 128 + r32) * 4 + q]
                            + pf[(2 * 128 + r32) * 4 + q]
                            + pf[(3 * 128 + r32) * 4 + q]
                            + __ldg(b_pre + q);
            const float ang = tanhf(sum) * PI_F;
            float cc, ss;
            sincosf(0.5f * ang, &ss, &cc);
            cs[(s * 32 + r32) * 4 + q] = make_float2(cc, ss);
        }
        __syncthreads();
    }

    // ---- circuit: one thread per row ----
    float cw[4], sw[4];
#pragma unroll
    for (int q = 0; q < 4; ++q) {
        const float2 v = cs[tid * 4 + q];
        cw[q] = v.x;
        sw[q] = v.y;
    }

    float sr[16], si[16];
#pragma unroll
    for (int i = 0; i < 16; ++i) {
        sr[i] = ((i & 8) ? sw[0] : cw[0]) * ((i & 4) ? sw[1] : cw[1]) *
                ((i & 2) ? sw[2] : cw[2]) * ((i & 1) ? sw[3] : cw[3]);
        si[i] = 0.f;
    }

#pragma unroll 1
    for (int h = 0; h < 2; ++h) {
        const float4 (*gb)[2] = &g_sh[h * 12];
        do_layer<1>(sr, si, gb + 0);
        do_layer<2>(sr, si, gb + 4);
        do_layer<3>(sr, si, gb + 8);
    }

    float e0 = 0.f, e1 = 0.f, e2 = 0.f, e3 = 0.f;
#pragma unroll
    for (int i = 0; i < 16; ++i) {
        const float pr = sr[i] * sr[i] + si[i] * si[i];
        e0 += (i & 8) ? -pr : pr;
        e1 += (i & 4) ? -pr : pr;
        e2 += (i & 2) ? -pr : pr;
        e3 += (i & 1) ? -pr : pr;
    }

    const long row = rowBlk + tid;
    if (row >= B) return;

    float o[10];
#pragma unroll
    for (int c = 0; c < 10; ++c) {
        o[c] = bpost_sh[c]
             + e0 * wpost_sh[c * 4 + 0] + e1 * wpost_sh[c * 4 + 1]
             + e2 * wpost_sh[c * 4 + 2] + e3 * wpost_sh[c * 4 + 3];
    }
    float2* op = reinterpret_cast<float2*>(out + row * 10);
#pragma unroll
    for (int c = 0; c < 5; ++c) op[c] = make_float2(o[2 * c], o[2 * c + 1]);
}

extern "C" void kernel_launch(void* const* d_in, const int* in_sizes, int n_in,
                              void* d_out, int out_size) {
    const float* x    = (const float*)d_in[0];
    const float* Wpre = (const float*)d_in[1];
    const float* bpre = (const float*)d_in[2];
    const float* qw   = (const float*)d_in[3];
    const float* Wpo  = (const float*)d_in[4];
    const float* bpo  = (const float*)d_in[5];
    float* out = (float*)d_out;

    const int B = in_sizes[0] / 512;
    const int grid = (B + 127) / 128;
    vqc_fused<<<grid, 128>>>((const float4*)x, (const float4*)Wpre, bpre, qw,
                             Wpo, bpo, out, B);
}

// round 5
// speedup vs baseline: 1.3540x; 1.0444x over previous
#include <cuda_runtime.h>

#define PI_F 3.14159265358979323846f

// scratch: pre-activations pre[B][4]
__device__ float g_pre[65536 * 4];

// ---------------------------------------------------------------------------
// fold: butterfly step that merges two accumulators while halving lane span.
// Lanes with bit m CLEAR end up with `a` reduced over the xor-m pair;
// lanes with bit m SET end up with `b` reduced over the xor-m pair.
// ---------------------------------------------------------------------------
__device__ __forceinline__ float foldf(float a, float b, int m, int lane) {
    const float s = (lane & m) ? a : b;
    const float r = __shfl_xor_sync(0xffffffffu, s, m);
    return (((lane & m) ? b : a) + r);
}

__device__ __forceinline__ float dot4acc(const float4 a, const float4 b,
                                         float acc) {
    return fmaf(a.x, b.x, fmaf(a.y, b.y, fmaf(a.z, b.z,
           fmaf(a.w, b.w, acc))));
}

// ---------------------------------------------------------------------------
// K1: GEMV pre = x @ W_pre^T. Warp per 2 rows per iteration, 8 rows per warp.
// 8 independent LDG.128 in flight per iteration, 9 shuffles per 2 rows,
// 8 coalesced 4B stores. No barriers, no smem.
// ---------------------------------------------------------------------------
__global__ __launch_bounds__(256, 2) void gemv_kernel(
    const float4* __restrict__ x4,      // [B,128] float4
    const float4* __restrict__ Wpre4,   // [4,128] float4
    int B)
{
    const int lane  = threadIdx.x & 31;
    const int gwarp = (blockIdx.x * 256 + threadIdx.x) >> 5;

    // W_pre resident: wv[it][q] covers cols it*128 + lane*4 .. +3
    float4 wv[4][4];
#pragma unroll
    for (int it = 0; it < 4; ++it)
#pragma unroll
        for (int q = 0; q < 4; ++q)
            wv[it][q] = Wpre4[q * 128 + it * 32 + lane];

    const int rowBase = gwarp * 8;

#pragma unroll 1
    for (int pi = 0; pi < 4; ++pi) {
        int r0 = rowBase + pi * 2;
        int r1 = r0 + 1;
        if (r0 >= B) r0 = B - 1;
        if (r1 >= B) r1 = B - 1;

        // 8 independent coalesced loads (front-batched by ptxas)
        float4 xv0[4], xv1[4];
#pragma unroll
        for (int it = 0; it < 4; ++it)
            xv0[it] = x4[(long)r0 * 128 + it * 32 + lane];
#pragma unroll
        for (int it = 0; it < 4; ++it)
            xv1[it] = x4[(long)r1 * 128 + it * 32 + lane];

        float a0 = 0.f, a1 = 0.f, a2 = 0.f, a3 = 0.f;
        float b0 = 0.f, b1 = 0.f, b2 = 0.f, b3 = 0.f;
#pragma unroll
        for (int it = 0; it < 4; ++it) {
            a0 = dot4acc(xv0[it], wv[it][0], a0);
            a1 = dot4acc(xv0[it], wv[it][1], a1);
            a2 = dot4acc(xv0[it], wv[it][2], a2);
            a3 = dot4acc(xv0[it], wv[it][3], a3);
            b0 = dot4acc(xv1[it], wv[it][0], b0);
            b1 = dot4acc(xv1[it], wv[it][1], b1);
            b2 = dot4acc(xv1[it], wv[it][2], b2);
            b3 = dot4acc(xv1[it], wv[it][3], b3);
        }

        // packed reduction: 9 shuffles for 8 accumulators.
        // After fold16/fold8/fold4 + xor2 + xor1:
        //   lane bit4 selects the row (0 -> r0/a, 1 -> r1/b)
        //   lane bits [3:2] select the qubit q
        //   lanes with (lane&3)==0 hold the fully-reduced value.
        const float t0 = foldf(a0, b0, 16, lane);
        const float t1 = foldf(a1, b1, 16, lane);
        const float t2 = foldf(a2, b2, 16, lane);
        const float t3 = foldf(a3, b3, 16, lane);
        const float u0 = foldf(t0, t2, 8, lane);
        const float u1 = foldf(t1, t3, 8, lane);
        float v = foldf(u0, u1, 4, lane);
        v += __shfl_xor_sync(0xffffffffu, v, 2);
        v += __shfl_xor_sync(0xffffffffu, v, 1);

        if ((lane & 3) == 0) {
            const int rsel = lane >> 4;
            const int q = (lane >> 2) & 3;     // FIXED mapping
            g_pre[(long)(rsel ? r1 : r0) * 4 + q] = v;
        }
    }
}

// ---------------------------------------------------------------------------
// circuit machinery (register-resident 16-amplitude state)
// ---------------------------------------------------------------------------
template <int ST>
__device__ __forceinline__ void apply1q(float* sr, float* si,
                                        const float4 g0, const float4 g1) {
#pragma unroll
    for (int m = 0; m < 8; ++m) {
        const int i0 = ((m & ~(ST - 1)) << 1) | (m & (ST - 1));
        const int i1 = i0 + ST;
        const float ar = sr[i0], ai = si[i0];
        const float br = sr[i1], bi = si[i1];
        sr[i0] = g0.x * ar - g0.y * ai + g0.z * br - g0.w * bi;
        si[i0] = g0.x * ai + g0.y * ar + g0.z * bi + g0.w * br;
        sr[i1] = g1.x * ar - g1.y * ai + g1.z * br - g1.w * bi;
        si[i1] = g1.x * ai + g1.y * ar + g1.z * bi + g1.w * br;
    }
}

template <int CM, int TM>
__device__ __forceinline__ void cnot(float* sr, float* si) {
#pragma unroll
    for (int i = 0; i < 16; ++i) {
        if ((i & CM) && !(i & TM)) {
            const int j = i | TM;
            float t;
            t = sr[i]; sr[i] = sr[j]; sr[j] = t;
            t = si[i]; si[i] = si[j]; si[j] = t;
        }
    }
}

template <int R>
__device__ __forceinline__ void do_layer(float* sr, float* si,
                                         const float4 (*g)[2]) {
    apply1q<8>(sr, si, g[0][0], g[0][1]);
    apply1q<4>(sr, si, g[1][0], g[1][1]);
    apply1q<2>(sr, si, g[2][0], g[2][1]);
    apply1q<1>(sr, si, g[3][0], g[3][1]);
    cnot<(8 >> 0), (8 >> ((0 + R) % 4))>(sr, si);
    cnot<(8 >> 1), (8 >> ((1 + R) % 4))>(sr, si);
    cnot<(8 >> 2), (8 >> ((2 + R) % 4))>(sr, si);
    cnot<(8 >> 3), (8 >> ((3 + R) % 4))>(sr, si);
}

// ---------------------------------------------------------------------------
// K2: quantum circuit + post-linear, one thread per row.
// ---------------------------------------------------------------------------
__global__ __launch_bounds__(256) void circuit_kernel(
    const float* __restrict__ b_pre,    // [4]
    const float* __restrict__ q_weights,// [6, 4, 3]
    const float* __restrict__ W_post,   // [10, 4]
    const float* __restrict__ b_post,   // [10]
    float* __restrict__ out,            // [B, 10]
    int B)
{
    __shared__ float4 g_sh[24][2];
    __shared__ float  wpost_sh[40];
    __shared__ float  bpost_sh[10];

    const int tid = threadIdx.x;
    if (tid < 24) {
        const float phi = q_weights[tid * 3 + 0];
        const float th  = q_weights[tid * 3 + 1];
        const float om  = q_weights[tid * 3 + 2];
        float c, s, cp, sp, cm, sm;
        sincosf(0.5f * th, &s, &c);
        sincosf(0.5f * (phi + om), &sp, &cp);
        sincosf(0.5f * (phi - om), &sm, &cm);
        g_sh[tid][0] = make_float4(cp * c, -sp * c, -cm * s, -sm * s);
        g_sh[tid][1] = make_float4(cm * s, -sm * s,  cp * c,  sp * c);
    }
    if (tid >= 32 && tid < 72)       wpost_sh[tid - 32] = W_post[tid - 32];
    else if (tid >= 72 && tid < 82)  bpost_sh[tid - 72] = b_post[tid - 72];
    __syncthreads();

    const long row = (long)blockIdx.x * 256 + tid;
    if (row >= B) return;

    const float4 p = *reinterpret_cast<const float4*>(g_pre + row * 4);

    float cw[4], sw[4];
    {
        float ang;
        ang = tanhf(p.x + __ldg(b_pre + 0)) * PI_F;
        sincosf(0.5f * ang, &sw[0], &cw[0]);
        ang = tanhf(p.y + __ldg(b_pre + 1)) * PI_F;
        sincosf(0.5f * ang, &sw[1], &cw[1]);
        ang = tanhf(p.z + __ldg(b_pre + 2)) * PI_F;
        sincosf(0.5f * ang, &sw[2], &cw[2]);
        ang = tanhf(p.w + __ldg(b_pre + 3)) * PI_F;
        sincosf(0.5f * ang, &sw[3], &cw[3]);
    }

    float sr[16], si[16];
#pragma unroll
    for (int i = 0; i < 16; ++i) {
        sr[i] = ((i & 8) ? sw[0] : cw[0]) * ((i & 4) ? sw[1] : cw[1]) *
                ((i & 2) ? sw[2] : cw[2]) * ((i & 1) ? sw[3] : cw[3]);
        si[i] = 0.f;
    }

#pragma unroll 1
    for (int h = 0; h < 2; ++h) {
        const float4 (*gb)[2] = &g_sh[h * 12];
        do_layer<1>(sr, si, gb + 0);
        do_layer<2>(sr, si, gb + 4);
        do_layer<3>(sr, si, gb + 8);
    }

    float e0 = 0.f, e1 = 0.f, e2 = 0.f, e3 = 0.f;
#pragma unroll
    for (int i = 0; i < 16; ++i) {
        const float pr = sr[i] * sr[i] + si[i] * si[i];
        e0 += (i & 8) ? -pr : pr;
        e1 += (i & 4) ? -pr : pr;
        e2 += (i & 2) ? -pr : pr;
        e3 += (i & 1) ? -pr : pr;
    }

    float o[10];
#pragma unroll
    for (int c = 0; c < 10; ++c) {
        o[c] = bpost_sh[c]
             + e0 * wpost_sh[c * 4 + 0] + e1 * wpost_sh[c * 4 + 1]
             + e2 * wpost_sh[c * 4 + 2] + e3 * wpost_sh[c * 4 + 3];
    }
    float2* op = reinterpret_cast<float2*>(out + row * 10);
#pragma unroll
    for (int c = 0; c < 5; ++c) op[c] = make_float2(o[2 * c], o[2 * c + 1]);
}

extern "C" void kernel_launch(void* const* d_in, const int* in_sizes, int n_in,
                              void* d_out, int out_size) {
    const float* x    = (const float*)d_in[0];
    const float* Wpre = (const float*)d_in[1];
    const float* bpre = (const float*)d_in[2];
    const float* qw   = (const float*)d_in[3];
    const float* Wpo  = (const float*)d_in[4];
    const float* bpo  = (const float*)d_in[5];
    float* out = (float*)d_out;

    const int B = in_sizes[0] / 512;

    // K1: 8 rows per warp, 8 warps per block -> 64 rows per block
    const int grid1 = (B + 63) / 64;
    gemv_kernel<<<grid1, 256>>>((const float4*)x, (const float4*)Wpre, B);

    // K2: one thread per row
    const int grid2 = (B + 255) / 256;
    circuit_kernel<<<grid2, 256>>>(bpre, qw, Wpo, bpo, out, B);
}